// round 12
// baseline (speedup 1.0000x reference)
#include <cuda_runtime.h>
#include <cuda_bf16.h>
#include <cstdint>

#define CC   64
#define CINN 66
#define LL   40960
#define WW   256
#define TP   256          // pixels per block (2 old tiles)
#define NTHR 512
#define NINST 32
#define NPARAMS 8513

#define OFF_W0 0
#define OFF_W1 4224
#define OFF_W2 8320
#define OFF_B0 8384
#define OFF_B1 8448
#define OFF_B2 8512
#define MASK_BIAS_SHIFT 2.19f

#define K1  80     // layer-1 K padded (66 -> 80, 5 k-steps)
#define KS1 80     // element stride, 160B rows
#define KS2 72     // layer-2 element stride, 144B rows

// ---- precomputed bf16-split operands (device globals; allocation-free) ----
__device__ __align__(16) uint16_t gXh[4 * LL * KS1];
__device__ __align__(16) uint16_t gXl[4 * LL * KS1];
#define WIMG_U16 19456
__device__ __align__(16) uint16_t gW[NINST * WIMG_U16];

// ---- GEMM smem byte offsets ----
#define W0H_O 0
#define W0L_O 10240
#define W1H_O 20480
#define W1L_O 29696
#define XH_O  38912     // 256*80*2 = 40960
#define XL_O  79872
#define HH_O  38912     // aliases X (dead after layer-1), 256*72*2 = 36864
#define HL_O  75776
#define MISC_O 120832
#define SMEM_TOTAL (MISC_O + 784 + 2048)   // biases/w2/b2 + sPart[2][256]

__device__ __forceinline__ void bsplit(float v, uint16_t* hi, uint16_t* lo) {
    __nv_bfloat16 bh = __float2bfloat16(v);
    float r = v - __bfloat162float(bh);
    __nv_bfloat16 bl = __float2bfloat16(r);
    *hi = *(uint16_t*)&bh;
    *lo = *(uint16_t*)&bl;
}
__device__ __forceinline__ uint32_t smem_u32(const void* p) {
    uint32_t a;
    asm("{ .reg .u64 t; cvta.to.shared.u64 t, %1; cvt.u32.u64 %0, t; }" : "=r"(a) : "l"(p));
    return a;
}
__device__ __forceinline__ void ldsm4(uint32_t* r, uint32_t addr) {
    asm volatile("ldmatrix.sync.aligned.m8n8.x4.shared.b16 {%0,%1,%2,%3}, [%4];"
                 : "=r"(r[0]), "=r"(r[1]), "=r"(r[2]), "=r"(r[3]) : "r"(addr));
}
__device__ __forceinline__ void mma16816(float* c, const uint32_t* a, uint32_t b0, uint32_t b1) {
    asm volatile(
        "mma.sync.aligned.m16n8k16.row.col.f32.bf16.bf16.f32 "
        "{%0,%1,%2,%3}, {%4,%5,%6,%7}, {%8,%9}, {%0,%1,%2,%3};"
        : "+f"(c[0]), "+f"(c[1]), "+f"(c[2]), "+f"(c[3])
        : "r"(a[0]), "r"(a[1]), "r"(a[2]), "r"(a[3]), "r"(b0), "r"(b1));
}

// ============ prep kernel 1: X -> bf16 hi/lo, [img][px][80] ============
__global__ __launch_bounds__(256)
void prep_x_kernel(const float* __restrict__ x)
{
    __shared__ __align__(16) float stage[128 * 89];
    const int tile = blockIdx.x;
    const int img  = blockIdx.y;
    const int tid  = threadIdx.x;
    const int l0   = tile * 128;

    const float* xb = x + (size_t)img * CC * LL + l0;
    for (int idx = tid; idx < CC * 128; idx += 256) {
        int ch = idx >> 7, px = idx & 127;
        stage[px * 89 + ch + 2] = xb[(size_t)ch * LL + px];
    }
    if (tid < 128) {
        stage[tid * 89 + 0] = (float)((l0 & (WW - 1)) + tid);
        stage[tid * 89 + 1] = (float)(l0 >> 8);
    }
    __syncthreads();

    for (int idx = tid; idx < 128 * KS1; idx += 256) {
        int px = idx / KS1, k = idx - px * KS1;
        float v = (k < CINN) ? stage[px * 89 + k] : 0.f;
        size_t o = ((size_t)img * LL + l0 + px) * KS1 + k;
        bsplit(v, &gXh[o], &gXl[o]);
    }
}

// ============ prep kernel 2: weights -> bf16 hi/lo flat images ============
__global__ __launch_bounds__(256)
void prep_w_kernel(const float* __restrict__ params)
{
    const int inst = blockIdx.x;
    const int tid  = threadIdx.x;
    const float* p = params + (size_t)inst * NPARAMS;
    uint16_t* w = gW + (size_t)inst * WIMG_U16;

    for (int idx = tid; idx < 64 * KS1; idx += 256) {
        int m = idx / KS1, k = idx - m * KS1;
        float v = (k < CINN) ? p[OFF_W0 + m * CINN + k] : 0.f;
        bsplit(v, &w[idx], &w[5120 + idx]);
    }
    for (int idx = tid; idx < 64 * KS2; idx += 256) {
        int m = idx / KS2, k = idx - m * KS2;
        float v = (k < 64) ? p[OFF_W1 + m * 64 + k] : 0.f;
        bsplit(v, &w[10240 + idx], &w[14848 + idx]);
    }
}

// ============ main GEMM kernel ============
extern __shared__ __align__(16) char smem[];

__global__ __launch_bounds__(NTHR, 1)
void condlane_mma_kernel(const float* __restrict__ params,
                         float* __restrict__ out)
{
    uint16_t* hh  = (uint16_t*)(smem + HH_O);
    uint16_t* hl  = (uint16_t*)(smem + HL_O);
    float*    sb0 = (float*)(smem + MISC_O);
    float*    sb1 = sb0 + 64;
    float*    sw2 = sb0 + 128;
    float*    sb2 = sb0 + 192;
    float*    sPart = sb0 + 196;        // [2][256]

    const int bx   = blockIdx.x;        // 0..159
    const int inst = blockIdx.y;        // 0..31
    const int img  = inst >> 3;
    const int tid  = threadIdx.x;
    const int wid  = tid >> 5;
    const int lane = tid & 31;
    const int l0   = bx * TP;
    const uint32_t sb = smem_u32(smem);

    // ---- flat copy-in: weights (2432 uint4), X hi/lo (2560 uint4 each) ----
    {
        const uint4* src = (const uint4*)(gW + (size_t)inst * WIMG_U16);
        uint4* dst = (uint4*)smem;
        for (int i = tid; i < 2432; i += NTHR) dst[i] = src[i];
        const uint4* srch = (const uint4*)(gXh + ((size_t)img * LL + l0) * KS1);
        const uint4* srcl = (const uint4*)(gXl + ((size_t)img * LL + l0) * KS1);
        uint4* dh = (uint4*)(smem + XH_O);
        uint4* dl = (uint4*)(smem + XL_O);
        for (int i = tid; i < 2560; i += NTHR) { dh[i] = srch[i]; dl[i] = srcl[i]; }
        const float* p = params + (size_t)inst * NPARAMS;
        if (tid < 64) {
            sb0[tid] = p[OFF_B0 + tid];
            sb1[tid] = p[OFF_B1 + tid];
            sw2[tid] = p[OFF_W2 + tid];
        }
        if (tid == 0) sb2[0] = p[OFF_B2] - MASK_BIAS_SHIFT;
    }
    __syncthreads();

    // ---- warp tiling: 16 warps = (2 m-halves) x (8 px-groups); 32 rows x 32 px each ----
    const int mh = wid & 1;
    const int ng = wid >> 1;            // 0..7
    const int g  = lane >> 2;
    const int t  = lane & 3;

    const int aRow = (lane & 7) + ((lane >> 3) & 1) * 8;
    const int aCol = (lane >> 4) * 8;
    const int bRow = (lane & 7) + (lane >> 4) * 8;
    const int bCol = ((lane >> 3) & 1) * 8;

    float acc[2][4][4];
    #pragma unroll
    for (int i = 0; i < 2; i++)
        #pragma unroll
        for (int j = 0; j < 4; j++)
            #pragma unroll
            for (int q = 0; q < 4; q++) acc[i][j][q] = 0.f;

    // ======== layer 1: K=80 (5 k-steps), reuse-ordered 3-pass split ========
    {
        uint32_t aH = sb + W0H_O + ((mh * 32 + aRow) * KS1 + aCol) * 2;
        uint32_t bH = sb + XH_O + ((ng * 32 + bRow) * KS1 + bCol) * 2;
        const uint32_t ALO = W0L_O - W0H_O;      // 10240
        const uint32_t BLO = XL_O - XH_O;        // 40960
        const uint32_t AMT = 16 * KS1 * 2;       // 2560
        const uint32_t BNT = 16 * KS1 * 2;
        #pragma unroll
        for (int ks = 0; ks < K1 / 16; ks++) {
            uint32_t kb = ks * 32;
            uint32_t ah[2][4], al[2][4], bh[2][4], bl[2][4];
            ldsm4(bh[0], bH + kb);
            ldsm4(bh[1], bH + BNT + kb);
            ldsm4(ah[0], aH + kb);
            ldsm4(ah[1], aH + AMT + kb);
            #pragma unroll
            for (int mt = 0; mt < 2; mt++)
                #pragma unroll
                for (int nt = 0; nt < 4; nt++)
                    mma16816(acc[mt][nt], ah[mt], bh[nt >> 1][(nt & 1) * 2], bh[nt >> 1][(nt & 1) * 2 + 1]);
            ldsm4(al[0], aH + ALO + kb);
            ldsm4(al[1], aH + ALO + AMT + kb);
            #pragma unroll
            for (int mt = 0; mt < 2; mt++)
                #pragma unroll
                for (int nt = 0; nt < 4; nt++)
                    mma16816(acc[mt][nt], al[mt], bh[nt >> 1][(nt & 1) * 2], bh[nt >> 1][(nt & 1) * 2 + 1]);
            ldsm4(bl[0], bH + BLO + kb);
            ldsm4(bl[1], bH + BLO + BNT + kb);
            #pragma unroll
            for (int mt = 0; mt < 2; mt++)
                #pragma unroll
                for (int nt = 0; nt < 4; nt++)
                    mma16816(acc[mt][nt], ah[mt], bl[nt >> 1][(nt & 1) * 2], bl[nt >> 1][(nt & 1) * 2 + 1]);
        }
    }
    __syncthreads();   // all reads of X done before H overwrites it

    // ---- epilogue 1: relu(C1 + b0) -> H [px][ch] bf16 hi/lo ----
    #pragma unroll
    for (int mt = 0; mt < 2; mt++)
        #pragma unroll
        for (int nt = 0; nt < 4; nt++) {
            int r0  = mh * 32 + mt * 16 + g;
            int px0 = ng * 32 + nt * 8 + t * 2;
            float v00 = acc[mt][nt][0] + sb0[r0];     v00 = v00 > 0.f ? v00 : 0.f;
            float v01 = acc[mt][nt][1] + sb0[r0];     v01 = v01 > 0.f ? v01 : 0.f;
            float v10 = acc[mt][nt][2] + sb0[r0 + 8]; v10 = v10 > 0.f ? v10 : 0.f;
            float v11 = acc[mt][nt][3] + sb0[r0 + 8]; v11 = v11 > 0.f ? v11 : 0.f;
            bsplit(v00, &hh[px0 * KS2 + r0],           &hl[px0 * KS2 + r0]);
            bsplit(v01, &hh[(px0 + 1) * KS2 + r0],     &hl[(px0 + 1) * KS2 + r0]);
            bsplit(v10, &hh[px0 * KS2 + r0 + 8],       &hl[px0 * KS2 + r0 + 8]);
            bsplit(v11, &hh[(px0 + 1) * KS2 + r0 + 8], &hl[(px0 + 1) * KS2 + r0 + 8]);
        }
    __syncthreads();

    // ======== layer 2: K=64 (4 k-steps) ========
    #pragma unroll
    for (int i = 0; i < 2; i++)
        #pragma unroll
        for (int j = 0; j < 4; j++)
            #pragma unroll
            for (int q = 0; q < 4; q++) acc[i][j][q] = 0.f;
    {
        uint32_t aH = sb + W1H_O + ((mh * 32 + aRow) * KS2 + aCol) * 2;
        uint32_t bH = sb + HH_O + ((ng * 32 + bRow) * KS2 + bCol) * 2;
        const uint32_t ALO = W1L_O - W1H_O;      // 9216
        const uint32_t BLO = HL_O - HH_O;        // 36864
        const uint32_t AMT = 16 * KS2 * 2;       // 2304
        const uint32_t BNT = 16 * KS2 * 2;
        #pragma unroll
        for (int ks = 0; ks < 4; ks++) {
            uint32_t kb = ks * 32;
            uint32_t ah[2][4], al[2][4], bh[2][4], bl[2][4];
            ldsm4(bh[0], bH + kb);
            ldsm4(bh[1], bH + BNT + kb);
            ldsm4(ah[0], aH + kb);
            ldsm4(ah[1], aH + AMT + kb);
            #pragma unroll
            for (int mt = 0; mt < 2; mt++)
                #pragma unroll
                for (int nt = 0; nt < 4; nt++)
                    mma16816(acc[mt][nt], ah[mt], bh[nt >> 1][(nt & 1) * 2], bh[nt >> 1][(nt & 1) * 2 + 1]);
            ldsm4(al[0], aH + ALO + kb);
            ldsm4(al[1], aH + ALO + AMT + kb);
            #pragma unroll
            for (int mt = 0; mt < 2; mt++)
                #pragma unroll
                for (int nt = 0; nt < 4; nt++)
                    mma16816(acc[mt][nt], al[mt], bh[nt >> 1][(nt & 1) * 2], bh[nt >> 1][(nt & 1) * 2 + 1]);
            ldsm4(bl[0], bH + BLO + kb);
            ldsm4(bl[1], bH + BLO + BNT + kb);
            #pragma unroll
            for (int mt = 0; mt < 2; mt++)
                #pragma unroll
                for (int nt = 0; nt < 4; nt++)
                    mma16816(acc[mt][nt], ah[mt], bl[nt >> 1][(nt & 1) * 2], bl[nt >> 1][(nt & 1) * 2 + 1]);
        }
    }

    // ---- epilogue 2 + layer 3 in registers ----
    float part[8];
    #pragma unroll
    for (int i = 0; i < 8; i++) part[i] = 0.f;
    #pragma unroll
    for (int mt = 0; mt < 2; mt++)
        #pragma unroll
        for (int nt = 0; nt < 4; nt++) {
            int r0 = mh * 32 + mt * 16 + g;
            float w2a = sw2[r0], w2b = sw2[r0 + 8];
            float v00 = acc[mt][nt][0] + sb1[r0];     v00 = v00 > 0.f ? v00 : 0.f;
            float v01 = acc[mt][nt][1] + sb1[r0];     v01 = v01 > 0.f ? v01 : 0.f;
            float v10 = acc[mt][nt][2] + sb1[r0 + 8]; v10 = v10 > 0.f ? v10 : 0.f;
            float v11 = acc[mt][nt][3] + sb1[r0 + 8]; v11 = v11 > 0.f ? v11 : 0.f;
            part[nt * 2]     += w2a * v00 + w2b * v10;
            part[nt * 2 + 1] += w2a * v01 + w2b * v11;
        }
    #pragma unroll
    for (int i = 0; i < 8; i++) {
        part[i] += __shfl_xor_sync(0xffffffffu, part[i], 4);
        part[i] += __shfl_xor_sync(0xffffffffu, part[i], 8);
        part[i] += __shfl_xor_sync(0xffffffffu, part[i], 16);
    }
    if (g == 0) {
        #pragma unroll
        for (int nt = 0; nt < 4; nt++) {
            int px0 = ng * 32 + nt * 8 + t * 2;
            sPart[mh * 256 + px0]     = part[nt * 2];
            sPart[mh * 256 + px0 + 1] = part[nt * 2 + 1];
        }
    }
    __syncthreads();

    if (tid < TP) {
        out[(size_t)inst * LL + l0 + tid] = sb2[0] + sPart[tid] + sPart[256 + tid];
    }
}

extern "C" void kernel_launch(void* const* d_in, const int* in_sizes, int n_in,
                              void* d_out, int out_size)
{
    const float* x      = (const float*)d_in[0];
    const float* params = (const float*)d_in[1];
    float* out = (float*)d_out;
    (void)in_sizes; (void)n_in; (void)out_size;

    cudaFuncSetAttribute(condlane_mma_kernel,
                         cudaFuncAttributeMaxDynamicSharedMemorySize, SMEM_TOTAL);

    dim3 gx(LL / 128, 4);
    prep_x_kernel<<<gx, 256>>>(x);
    prep_w_kernel<<<NINST, 256>>>(params);

    dim3 grid(LL / TP, NINST);   // 160 x 32
    condlane_mma_kernel<<<grid, NTHR, SMEM_TOTAL>>>(params, out);
}

// round 13
// speedup vs baseline: 1.5014x; 1.5014x over previous
#include <cuda_runtime.h>
#include <cuda_bf16.h>
#include <cstdint>

#define CC   64
#define CINN 66
#define LL   40960
#define WW   256
#define TP   128
#define NTHR 256
#define NINST 32
#define NPARAMS 8513

#define OFF_W0 0
#define OFF_W1 4224
#define OFF_W2 8320
#define OFF_B0 8384
#define OFF_B1 8448
#define OFF_B2 8512
#define MASK_BIAS_SHIFT 2.19f

#define KS 72      // element stride both layers, 144B rows (conflict-free ldsm)

// ---- precomputed bf16-split operands (device globals; allocation-free) ----
// gX: [img][px][72] hi/lo (64 channels + 8 zero pad; coords folded analytically)
__device__ __align__(16) uint16_t gXh[4 * LL * KS];
__device__ __align__(16) uint16_t gXl[4 * LL * KS];
// per-instance flat weight image: W0h | W0l | W1h | W1l, each 64*72 u16
#define WIMG_U16 18432
__device__ __align__(16) uint16_t gW[NINST * WIMG_U16];

// ---- GEMM smem byte offsets ----
#define W0H_O 0
#define W0L_O 9216
#define W1H_O 18432
#define W1L_O 27648
#define XH_O  36864     // 128*72*2 = 18432
#define XL_O  55296
#define HH_O  36864     // H aliases X exactly (same shape)
#define HL_O  55296
#define MISC_O 73728
#define SMEM_TOTAL (MISC_O + 2080)   // sb0f/sb1/sw2/sWx (64 ea) + sb2 + sPart[2][128]

__device__ __forceinline__ void bsplit(float v, uint16_t* hi, uint16_t* lo) {
    __nv_bfloat16 bh = __float2bfloat16(v);
    float r = v - __bfloat162float(bh);
    __nv_bfloat16 bl = __float2bfloat16(r);
    *hi = *(uint16_t*)&bh;
    *lo = *(uint16_t*)&bl;
}
__device__ __forceinline__ uint32_t smem_u32(const void* p) {
    uint32_t a;
    asm("{ .reg .u64 t; cvta.to.shared.u64 t, %1; cvt.u32.u64 %0, t; }" : "=r"(a) : "l"(p));
    return a;
}
__device__ __forceinline__ void cpasync16(uint32_t dst, const void* src) {
    asm volatile("cp.async.cg.shared.global [%0], [%1], 16;" :: "r"(dst), "l"(src) : "memory");
}
__device__ __forceinline__ void ldsm4(uint32_t* r, uint32_t addr) {
    asm volatile("ldmatrix.sync.aligned.m8n8.x4.shared.b16 {%0,%1,%2,%3}, [%4];"
                 : "=r"(r[0]), "=r"(r[1]), "=r"(r[2]), "=r"(r[3]) : "r"(addr));
}
__device__ __forceinline__ void mma16816(float* c, const uint32_t* a, uint32_t b0, uint32_t b1) {
    asm volatile(
        "mma.sync.aligned.m16n8k16.row.col.f32.bf16.bf16.f32 "
        "{%0,%1,%2,%3}, {%4,%5,%6,%7}, {%8,%9}, {%0,%1,%2,%3};"
        : "+f"(c[0]), "+f"(c[1]), "+f"(c[2]), "+f"(c[3])
        : "r"(a[0]), "r"(a[1]), "r"(a[2]), "r"(a[3]), "r"(b0), "r"(b1));
}

// ============ prep kernel 1: X channels -> bf16 hi/lo, [img][px][72] ============
__global__ __launch_bounds__(256)
void prep_x_kernel(const float* __restrict__ x)
{
    __shared__ __align__(16) float stage[TP * 89];
    const int tile = blockIdx.x;
    const int img  = blockIdx.y;
    const int tid  = threadIdx.x;
    const int l0   = tile * TP;

    const float* xb = x + (size_t)img * CC * LL + l0;
    for (int idx = tid; idx < CC * TP; idx += 256) {
        int ch = idx >> 7, px = idx & 127;
        stage[px * 89 + ch] = xb[(size_t)ch * LL + px];
    }
    __syncthreads();

    for (int idx = tid; idx < TP * KS; idx += 256) {
        int px = idx / KS, k = idx - px * KS;
        float v = (k < CC) ? stage[px * 89 + k] : 0.f;
        size_t o = ((size_t)img * LL + l0 + px) * KS + k;
        bsplit(v, &gXh[o], &gXl[o]);
    }
}

// ============ prep kernel 2: weights -> bf16 hi/lo flat images ============
// W0' drops the two coord columns: W0'[m][k] = w0[m][k+2], k<64
__global__ __launch_bounds__(256)
void prep_w_kernel(const float* __restrict__ params)
{
    const int inst = blockIdx.x;
    const int tid  = threadIdx.x;
    const float* p = params + (size_t)inst * NPARAMS;
    uint16_t* w = gW + (size_t)inst * WIMG_U16;

    for (int idx = tid; idx < 64 * KS; idx += 256) {
        int m = idx / KS, k = idx - m * KS;
        float v = (k < 64) ? p[OFF_W0 + m * CINN + k + 2] : 0.f;
        bsplit(v, &w[idx], &w[4608 + idx]);          // W0h, W0l
    }
    for (int idx = tid; idx < 64 * KS; idx += 256) {
        int m = idx / KS, k = idx - m * KS;
        float v = (k < 64) ? p[OFF_W1 + m * 64 + k] : 0.f;
        bsplit(v, &w[9216 + idx], &w[13824 + idx]);  // W1h, W1l
    }
}

// ============ main GEMM kernel ============
extern __shared__ __align__(16) char smem[];

__global__ __launch_bounds__(NTHR, 2)
void condlane_mma_kernel(const float* __restrict__ params,
                         float* __restrict__ out)
{
    uint16_t* hh  = (uint16_t*)(smem + HH_O);
    uint16_t* hl  = (uint16_t*)(smem + HL_O);
    float*    sb0f = (float*)(smem + MISC_O);   // b0 + w0[:,1]*y
    float*    sb1  = sb0f + 64;
    float*    sw2  = sb0f + 128;
    float*    sWx  = sb0f + 192;                // w0[:,0]
    float*    sb2  = sb0f + 256;
    float*    sPart = sb0f + 260;               // [2][128]

    const int bx   = blockIdx.x;
    const int inst = blockIdx.y;
    const int img  = inst >> 3;
    const int tid  = threadIdx.x;
    const int wid  = tid >> 5;
    const int lane = tid & 31;
    const int l0   = bx * TP;
    const uint32_t sb = smem_u32(smem);

    // ---- cp.async copy-in: weights (2304 uint4), X hi/lo (1152 uint4 each) ----
    {
        const uint4* wsrc = (const uint4*)(gW + (size_t)inst * WIMG_U16);
        for (int i = tid; i < 2304; i += NTHR)
            cpasync16(sb + i * 16, wsrc + i);
        const uint4* srch = (const uint4*)(gXh + ((size_t)img * LL + l0) * KS);
        const uint4* srcl = (const uint4*)(gXl + ((size_t)img * LL + l0) * KS);
        for (int i = tid; i < 1152; i += NTHR) {
            cpasync16(sb + XH_O + i * 16, srch + i);
            cpasync16(sb + XL_O + i * 16, srcl + i);
        }
        const float* p = params + (size_t)inst * NPARAMS;
        const float yc = (float)(l0 >> 8);
        if (tid < 64) {
            sb0f[tid] = p[OFF_B0 + tid] + p[OFF_W0 + tid * CINN + 1] * yc;
            sWx[tid]  = p[OFF_W0 + tid * CINN];
            sb1[tid]  = p[OFF_B1 + tid];
            sw2[tid]  = p[OFF_W2 + tid];
        }
        if (tid == 0) sb2[0] = p[OFF_B2] - MASK_BIAS_SHIFT;
        asm volatile("cp.async.commit_group;\ncp.async.wait_group 0;" ::: "memory");
    }
    __syncthreads();

    // ---- warp tiling: 8 warps = (2 m-halves) x (4 px-groups); 32 rows x 32 px ----
    const int mh = wid & 1;
    const int ng = wid >> 1;
    const int g  = lane >> 2;
    const int t  = lane & 3;

    const int aRow = (lane & 7) + ((lane >> 3) & 1) * 8;
    const int aCol = (lane >> 4) * 8;
    const int bRow = (lane & 7) + (lane >> 4) * 8;
    const int bCol = ((lane >> 3) & 1) * 8;

    const float xbase = (float)(l0 & (WW - 1));

    float acc[2][4][4];
    #pragma unroll
    for (int i = 0; i < 2; i++)
        #pragma unroll
        for (int j = 0; j < 4; j++)
            #pragma unroll
            for (int q = 0; q < 4; q++) acc[i][j][q] = 0.f;

    // ======== layer 1: C1 = W0' @ Xc, K=64 (4 k-steps), reuse-ordered 3-pass ========
    {
        uint32_t aH = sb + W0H_O + ((mh * 32 + aRow) * KS + aCol) * 2;
        uint32_t bH = sb + XH_O + ((ng * 32 + bRow) * KS + bCol) * 2;
        const uint32_t ALO = W0L_O - W0H_O;      // 9216
        const uint32_t BLO = XL_O - XH_O;        // 18432
        const uint32_t AMT = 16 * KS * 2;        // 2304
        const uint32_t BNT = 16 * KS * 2;
        #pragma unroll
        for (int ks = 0; ks < 4; ks++) {
            uint32_t kb = ks * 32;
            uint32_t ah[2][4], al[2][4], bh[2][4], bl[2][4];
            ldsm4(bh[0], bH + kb);
            ldsm4(bh[1], bH + BNT + kb);
            ldsm4(ah[0], aH + kb);
            ldsm4(ah[1], aH + AMT + kb);
            #pragma unroll
            for (int mt = 0; mt < 2; mt++)
                #pragma unroll
                for (int nt = 0; nt < 4; nt++)
                    mma16816(acc[mt][nt], ah[mt], bh[nt >> 1][(nt & 1) * 2], bh[nt >> 1][(nt & 1) * 2 + 1]);
            ldsm4(al[0], aH + ALO + kb);
            ldsm4(al[1], aH + ALO + AMT + kb);
            #pragma unroll
            for (int mt = 0; mt < 2; mt++)
                #pragma unroll
                for (int nt = 0; nt < 4; nt++)
                    mma16816(acc[mt][nt], al[mt], bh[nt >> 1][(nt & 1) * 2], bh[nt >> 1][(nt & 1) * 2 + 1]);
            ldsm4(bl[0], bH + BLO + kb);
            ldsm4(bl[1], bH + BLO + BNT + kb);
            #pragma unroll
            for (int mt = 0; mt < 2; mt++)
                #pragma unroll
                for (int nt = 0; nt < 4; nt++)
                    mma16816(acc[mt][nt], ah[mt], bl[nt >> 1][(nt & 1) * 2], bl[nt >> 1][(nt & 1) * 2 + 1]);
        }
    }
    __syncthreads();   // all reads of X done before H overwrites it

    // ---- epilogue 1: relu(C1 + b0' + w0x*xcoord) -> H [px][ch] bf16 hi/lo ----
    #pragma unroll
    for (int mt = 0; mt < 2; mt++)
        #pragma unroll
        for (int nt = 0; nt < 4; nt++) {
            int r0  = mh * 32 + mt * 16 + g;
            int px0 = ng * 32 + nt * 8 + t * 2;
            float xc0 = xbase + (float)px0;
            float xc1 = xc0 + 1.f;
            float ba = sb0f[r0],     wa = sWx[r0];
            float bb = sb0f[r0 + 8], wb = sWx[r0 + 8];
            float v00 = acc[mt][nt][0] + ba + wa * xc0; v00 = v00 > 0.f ? v00 : 0.f;
            float v01 = acc[mt][nt][1] + ba + wa * xc1; v01 = v01 > 0.f ? v01 : 0.f;
            float v10 = acc[mt][nt][2] + bb + wb * xc0; v10 = v10 > 0.f ? v10 : 0.f;
            float v11 = acc[mt][nt][3] + bb + wb * xc1; v11 = v11 > 0.f ? v11 : 0.f;
            bsplit(v00, &hh[px0 * KS + r0],           &hl[px0 * KS + r0]);
            bsplit(v01, &hh[(px0 + 1) * KS + r0],     &hl[(px0 + 1) * KS + r0]);
            bsplit(v10, &hh[px0 * KS + r0 + 8],       &hl[px0 * KS + r0 + 8]);
            bsplit(v11, &hh[(px0 + 1) * KS + r0 + 8], &hl[(px0 + 1) * KS + r0 + 8]);
        }
    __syncthreads();

    // ======== layer 2: C2 = W1 @ H, K=64 (4 k-steps) ========
    #pragma unroll
    for (int i = 0; i < 2; i++)
        #pragma unroll
        for (int j = 0; j < 4; j++)
            #pragma unroll
            for (int q = 0; q < 4; q++) acc[i][j][q] = 0.f;
    {
        uint32_t aH = sb + W1H_O + ((mh * 32 + aRow) * KS + aCol) * 2;
        uint32_t bH = sb + HH_O + ((ng * 32 + bRow) * KS + bCol) * 2;
        const uint32_t ALO = W1L_O - W1H_O;      // 9216
        const uint32_t BLO = HL_O - HH_O;        // 18432
        const uint32_t AMT = 16 * KS * 2;
        const uint32_t BNT = 16 * KS * 2;
        #pragma unroll
        for (int ks = 0; ks < 4; ks++) {
            uint32_t kb = ks * 32;
            uint32_t ah[2][4], al[2][4], bh[2][4], bl[2][4];
            ldsm4(bh[0], bH + kb);
            ldsm4(bh[1], bH + BNT + kb);
            ldsm4(ah[0], aH + kb);
            ldsm4(ah[1], aH + AMT + kb);
            #pragma unroll
            for (int mt = 0; mt < 2; mt++)
                #pragma unroll
                for (int nt = 0; nt < 4; nt++)
                    mma16816(acc[mt][nt], ah[mt], bh[nt >> 1][(nt & 1) * 2], bh[nt >> 1][(nt & 1) * 2 + 1]);
            ldsm4(al[0], aH + ALO + kb);
            ldsm4(al[1], aH + ALO + AMT + kb);
            #pragma unroll
            for (int mt = 0; mt < 2; mt++)
                #pragma unroll
                for (int nt = 0; nt < 4; nt++)
                    mma16816(acc[mt][nt], al[mt], bh[nt >> 1][(nt & 1) * 2], bh[nt >> 1][(nt & 1) * 2 + 1]);
            ldsm4(bl[0], bH + BLO + kb);
            ldsm4(bl[1], bH + BLO + BNT + kb);
            #pragma unroll
            for (int mt = 0; mt < 2; mt++)
                #pragma unroll
                for (int nt = 0; nt < 4; nt++)
                    mma16816(acc[mt][nt], ah[mt], bl[nt >> 1][(nt & 1) * 2], bl[nt >> 1][(nt & 1) * 2 + 1]);
        }
    }

    // ---- epilogue 2 + layer 3 in registers ----
    float part[8];
    #pragma unroll
    for (int i = 0; i < 8; i++) part[i] = 0.f;
    #pragma unroll
    for (int mt = 0; mt < 2; mt++)
        #pragma unroll
        for (int nt = 0; nt < 4; nt++) {
            int r0 = mh * 32 + mt * 16 + g;
            float w2a = sw2[r0], w2b = sw2[r0 + 8];
            float v00 = acc[mt][nt][0] + sb1[r0];     v00 = v00 > 0.f ? v00 : 0.f;
            float v01 = acc[mt][nt][1] + sb1[r0];     v01 = v01 > 0.f ? v01 : 0.f;
            float v10 = acc[mt][nt][2] + sb1[r0 + 8]; v10 = v10 > 0.f ? v10 : 0.f;
            float v11 = acc[mt][nt][3] + sb1[r0 + 8]; v11 = v11 > 0.f ? v11 : 0.f;
            part[nt * 2]     += w2a * v00 + w2b * v10;
            part[nt * 2 + 1] += w2a * v01 + w2b * v11;
        }
    #pragma unroll
    for (int i = 0; i < 8; i++) {
        part[i] += __shfl_xor_sync(0xffffffffu, part[i], 4);
        part[i] += __shfl_xor_sync(0xffffffffu, part[i], 8);
        part[i] += __shfl_xor_sync(0xffffffffu, part[i], 16);
    }
    if (g == 0) {
        #pragma unroll
        for (int nt = 0; nt < 4; nt++) {
            int px0 = ng * 32 + nt * 8 + t * 2;
            sPart[mh * 128 + px0]     = part[nt * 2];
            sPart[mh * 128 + px0 + 1] = part[nt * 2 + 1];
        }
    }
    __syncthreads();

    if (tid < TP) {
        out[(size_t)inst * LL + l0 + tid] = sb2[0] + sPart[tid] + sPart[128 + tid];
    }
}

extern "C" void kernel_launch(void* const* d_in, const int* in_sizes, int n_in,
                              void* d_out, int out_size)
{
    const float* x      = (const float*)d_in[0];
    const float* params = (const float*)d_in[1];
    float* out = (float*)d_out;
    (void)in_sizes; (void)n_in; (void)out_size;

    cudaFuncSetAttribute(condlane_mma_kernel,
                         cudaFuncAttributeMaxDynamicSharedMemorySize, SMEM_TOTAL);

    dim3 gx(LL / TP, 4);
    prep_x_kernel<<<gx, 256>>>(x);
    prep_w_kernel<<<NINST, 256>>>(params);

    dim3 grid(LL / TP, NINST);   // 320 x 32
    condlane_mma_kernel<<<grid, NTHR, SMEM_TOTAL>>>(params, out);
}

// round 14
// speedup vs baseline: 1.6582x; 1.1044x over previous
#include <cuda_runtime.h>
#include <cuda_bf16.h>
#include <cstdint>

#define CC   64
#define CINN 66
#define LL   40960
#define WW   256
#define TP   128
#define NTHR 256
#define NINST 32
#define NPARAMS 8513

#define OFF_W0 0
#define OFF_W1 4224
#define OFF_W2 8320
#define OFF_B0 8384
#define OFF_B1 8448
#define OFF_B2 8512
#define MASK_BIAS_SHIFT 2.19f

#define KS 72      // element stride both layers, 144B rows (conflict-free ldsm)

// ---- precomputed bf16-split operands (device globals; allocation-free) ----
__device__ __align__(16) uint16_t gXh[4 * LL * KS];
__device__ __align__(16) uint16_t gXl[4 * LL * KS];
#define WIMG_U16 18432
__device__ __align__(16) uint16_t gW[NINST * WIMG_U16];

// ---- GEMM smem byte offsets ----
#define W0H_O 0
#define W0L_O 9216
#define W1H_O 18432
#define W1L_O 27648
#define XH_O  36864     // 128*72*2 = 18432
#define XL_O  55296
#define HH_O  36864     // H aliases X exactly (same shape)
#define HL_O  55296
#define MISC_O 73728
#define SMEM_TOTAL (MISC_O + 2080)   // 75808 B -> 3 blocks/SM fit in 228KB

__device__ __forceinline__ void bsplit(float v, uint16_t* hi, uint16_t* lo) {
    __nv_bfloat16 bh = __float2bfloat16(v);
    float r = v - __bfloat162float(bh);
    __nv_bfloat16 bl = __float2bfloat16(r);
    *hi = *(uint16_t*)&bh;
    *lo = *(uint16_t*)&bl;
}
__device__ __forceinline__ uint32_t smem_u32(const void* p) {
    uint32_t a;
    asm("{ .reg .u64 t; cvta.to.shared.u64 t, %1; cvt.u32.u64 %0, t; }" : "=r"(a) : "l"(p));
    return a;
}
__device__ __forceinline__ void cpasync16(uint32_t dst, const void* src) {
    asm volatile("cp.async.cg.shared.global [%0], [%1], 16;" :: "r"(dst), "l"(src) : "memory");
}
__device__ __forceinline__ void ldsm4(uint32_t* r, uint32_t addr) {
    asm volatile("ldmatrix.sync.aligned.m8n8.x4.shared.b16 {%0,%1,%2,%3}, [%4];"
                 : "=r"(r[0]), "=r"(r[1]), "=r"(r[2]), "=r"(r[3]) : "r"(addr));
}
__device__ __forceinline__ void mma16816(float* c, const uint32_t* a, uint32_t b0, uint32_t b1) {
    asm volatile(
        "mma.sync.aligned.m16n8k16.row.col.f32.bf16.bf16.f32 "
        "{%0,%1,%2,%3}, {%4,%5,%6,%7}, {%8,%9}, {%0,%1,%2,%3};"
        : "+f"(c[0]), "+f"(c[1]), "+f"(c[2]), "+f"(c[3])
        : "r"(a[0]), "r"(a[1]), "r"(a[2]), "r"(a[3]), "r"(b0), "r"(b1));
}

// ============ prep kernel 1: X channels -> bf16 hi/lo, [img][px][72], u32 stores ============
__global__ __launch_bounds__(256)
void prep_x_kernel(const float* __restrict__ x)
{
    __shared__ __align__(16) float stage[TP * 89];
    const int tile = blockIdx.x;
    const int img  = blockIdx.y;
    const int tid  = threadIdx.x;
    const int l0   = tile * TP;

    const float* xb = x + (size_t)img * CC * LL + l0;
    for (int idx = tid; idx < CC * TP; idx += 256) {
        int ch = idx >> 7, px = idx & 127;
        stage[px * 89 + ch] = xb[(size_t)ch * LL + px];
    }
    __syncthreads();

    // pack two adjacent k per thread -> coalesced 4B stores
    uint32_t* gh = (uint32_t*)gXh;
    uint32_t* gl = (uint32_t*)gXl;
    for (int idx = tid; idx < TP * (KS / 2); idx += 256) {
        int px = idx / 36, kk = idx - px * 36;
        int k = kk * 2;
        float v0 = (k < CC) ? stage[px * 89 + k] : 0.f;
        float v1 = (k + 1 < CC) ? stage[px * 89 + k + 1] : 0.f;
        uint16_t h0, l0_, h1, l1;
        bsplit(v0, &h0, &l0_);
        bsplit(v1, &h1, &l1);
        size_t o = (((size_t)img * LL + l0 + px) * KS + k) >> 1;
        gh[o] = (uint32_t)h0 | ((uint32_t)h1 << 16);
        gl[o] = (uint32_t)l0_ | ((uint32_t)l1 << 16);
    }
}

// ============ prep kernel 2: weights -> bf16 hi/lo flat images ============
__global__ __launch_bounds__(256)
void prep_w_kernel(const float* __restrict__ params)
{
    const int inst = blockIdx.x;
    const int tid  = threadIdx.x;
    const float* p = params + (size_t)inst * NPARAMS;
    uint16_t* w = gW + (size_t)inst * WIMG_U16;

    for (int idx = tid; idx < 64 * KS; idx += 256) {
        int m = idx / KS, k = idx - m * KS;
        float v = (k < 64) ? p[OFF_W0 + m * CINN + k + 2] : 0.f;
        bsplit(v, &w[idx], &w[4608 + idx]);          // W0h, W0l
    }
    for (int idx = tid; idx < 64 * KS; idx += 256) {
        int m = idx / KS, k = idx - m * KS;
        float v = (k < 64) ? p[OFF_W1 + m * 64 + k] : 0.f;
        bsplit(v, &w[9216 + idx], &w[13824 + idx]);  // W1h, W1l
    }
}

// ============ main GEMM kernel ============
extern __shared__ __align__(16) char smem[];

__global__ __launch_bounds__(NTHR, 3)
void condlane_mma_kernel(const float* __restrict__ params,
                         float* __restrict__ out)
{
    uint16_t* hh  = (uint16_t*)(smem + HH_O);
    uint16_t* hl  = (uint16_t*)(smem + HL_O);
    float*    sb0f = (float*)(smem + MISC_O);   // b0 + w0[:,1]*y
    float*    sb1  = sb0f + 64;
    float*    sw2  = sb0f + 128;
    float*    sWx  = sb0f + 192;                // w0[:,0]
    float*    sb2  = sb0f + 256;
    float*    sPart = sb0f + 260;               // [2][128]

    const int bx   = blockIdx.x;
    const int inst = blockIdx.y;
    const int img  = inst >> 3;
    const int tid  = threadIdx.x;
    const int wid  = tid >> 5;
    const int lane = tid & 31;
    const int l0   = bx * TP;
    const uint32_t sb = smem_u32(smem);

    // ---- cp.async copy-in ----
    {
        const uint4* wsrc = (const uint4*)(gW + (size_t)inst * WIMG_U16);
        for (int i = tid; i < 2304; i += NTHR)
            cpasync16(sb + i * 16, wsrc + i);
        const uint4* srch = (const uint4*)(gXh + ((size_t)img * LL + l0) * KS);
        const uint4* srcl = (const uint4*)(gXl + ((size_t)img * LL + l0) * KS);
        for (int i = tid; i < 1152; i += NTHR) {
            cpasync16(sb + XH_O + i * 16, srch + i);
            cpasync16(sb + XL_O + i * 16, srcl + i);
        }
        const float* p = params + (size_t)inst * NPARAMS;
        const float yc = (float)(l0 >> 8);
        if (tid < 64) {
            sb0f[tid] = p[OFF_B0 + tid] + p[OFF_W0 + tid * CINN + 1] * yc;
            sWx[tid]  = p[OFF_W0 + tid * CINN];
            sb1[tid]  = p[OFF_B1 + tid];
            sw2[tid]  = p[OFF_W2 + tid];
        }
        if (tid == 0) sb2[0] = p[OFF_B2] - MASK_BIAS_SHIFT;
        asm volatile("cp.async.commit_group;\ncp.async.wait_group 0;" ::: "memory");
    }
    __syncthreads();

    // ---- warp tiling: 8 warps = (2 m-halves) x (4 px-groups); 32 rows x 32 px ----
    const int mh = wid & 1;
    const int ng = wid >> 1;
    const int g  = lane >> 2;
    const int t  = lane & 3;

    const int aRow = (lane & 7) + ((lane >> 3) & 1) * 8;
    const int aCol = (lane >> 4) * 8;
    const int bRow = (lane & 7) + (lane >> 4) * 8;
    const int bCol = ((lane >> 3) & 1) * 8;

    const float xbase = (float)(l0 & (WW - 1));

    float acc[2][4][4];
    #pragma unroll
    for (int i = 0; i < 2; i++)
        #pragma unroll
        for (int j = 0; j < 4; j++)
            #pragma unroll
            for (int q = 0; q < 4; q++) acc[i][j][q] = 0.f;

    // ======== layer 1: C1 = W0' @ Xc, K=64 (4 k-steps), reuse-ordered 3-pass ========
    {
        uint32_t aH = sb + W0H_O + ((mh * 32 + aRow) * KS + aCol) * 2;
        uint32_t bH = sb + XH_O + ((ng * 32 + bRow) * KS + bCol) * 2;
        const uint32_t ALO = W0L_O - W0H_O;      // 9216
        const uint32_t BLO = XL_O - XH_O;        // 18432
        const uint32_t AMT = 16 * KS * 2;        // 2304
        const uint32_t BNT = 16 * KS * 2;
        #pragma unroll
        for (int ks = 0; ks < 4; ks++) {
            uint32_t kb = ks * 32;
            uint32_t ah[2][4], al[2][4], bh[2][4], bl[2][4];
            ldsm4(bh[0], bH + kb);
            ldsm4(bh[1], bH + BNT + kb);
            ldsm4(ah[0], aH + kb);
            ldsm4(ah[1], aH + AMT + kb);
            #pragma unroll
            for (int mt = 0; mt < 2; mt++)
                #pragma unroll
                for (int nt = 0; nt < 4; nt++)
                    mma16816(acc[mt][nt], ah[mt], bh[nt >> 1][(nt & 1) * 2], bh[nt >> 1][(nt & 1) * 2 + 1]);
            ldsm4(al[0], aH + ALO + kb);
            ldsm4(al[1], aH + ALO + AMT + kb);
            #pragma unroll
            for (int mt = 0; mt < 2; mt++)
                #pragma unroll
                for (int nt = 0; nt < 4; nt++)
                    mma16816(acc[mt][nt], al[mt], bh[nt >> 1][(nt & 1) * 2], bh[nt >> 1][(nt & 1) * 2 + 1]);
            ldsm4(bl[0], bH + BLO + kb);
            ldsm4(bl[1], bH + BLO + BNT + kb);
            #pragma unroll
            for (int mt = 0; mt < 2; mt++)
                #pragma unroll
                for (int nt = 0; nt < 4; nt++)
                    mma16816(acc[mt][nt], ah[mt], bl[nt >> 1][(nt & 1) * 2], bl[nt >> 1][(nt & 1) * 2 + 1]);
        }
    }
    __syncthreads();   // all reads of X done before H overwrites it

    // ---- epilogue 1: relu(C1 + b0' + w0x*xcoord) -> H [px][ch] bf16 hi/lo ----
    #pragma unroll
    for (int mt = 0; mt < 2; mt++)
        #pragma unroll
        for (int nt = 0; nt < 4; nt++) {
            int r0  = mh * 32 + mt * 16 + g;
            int px0 = ng * 32 + nt * 8 + t * 2;
            float xc0 = xbase + (float)px0;
            float xc1 = xc0 + 1.f;
            float ba = sb0f[r0],     wa = sWx[r0];
            float bb = sb0f[r0 + 8], wb = sWx[r0 + 8];
            float v00 = acc[mt][nt][0] + ba + wa * xc0; v00 = v00 > 0.f ? v00 : 0.f;
            float v01 = acc[mt][nt][1] + ba + wa * xc1; v01 = v01 > 0.f ? v01 : 0.f;
            float v10 = acc[mt][nt][2] + bb + wb * xc0; v10 = v10 > 0.f ? v10 : 0.f;
            float v11 = acc[mt][nt][3] + bb + wb * xc1; v11 = v11 > 0.f ? v11 : 0.f;
            bsplit(v00, &hh[px0 * KS + r0],           &hl[px0 * KS + r0]);
            bsplit(v01, &hh[(px0 + 1) * KS + r0],     &hl[(px0 + 1) * KS + r0]);
            bsplit(v10, &hh[px0 * KS + r0 + 8],       &hl[px0 * KS + r0 + 8]);
            bsplit(v11, &hh[(px0 + 1) * KS + r0 + 8], &hl[(px0 + 1) * KS + r0 + 8]);
        }
    __syncthreads();

    // ======== layer 2: C2 = W1 @ H, K=64 (4 k-steps) ========
    #pragma unroll
    for (int i = 0; i < 2; i++)
        #pragma unroll
        for (int j = 0; j < 4; j++)
            #pragma unroll
            for (int q = 0; q < 4; q++) acc[i][j][q] = 0.f;
    {
        uint32_t aH = sb + W1H_O + ((mh * 32 + aRow) * KS + aCol) * 2;
        uint32_t bH = sb + HH_O + ((ng * 32 + bRow) * KS + bCol) * 2;
        const uint32_t ALO = W1L_O - W1H_O;      // 9216
        const uint32_t BLO = HL_O - HH_O;        // 18432
        const uint32_t AMT = 16 * KS * 2;
        const uint32_t BNT = 16 * KS * 2;
        #pragma unroll
        for (int ks = 0; ks < 4; ks++) {
            uint32_t kb = ks * 32;
            uint32_t ah[2][4], al[2][4], bh[2][4], bl[2][4];
            ldsm4(bh[0], bH + kb);
            ldsm4(bh[1], bH + BNT + kb);
            ldsm4(ah[0], aH + kb);
            ldsm4(ah[1], aH + AMT + kb);
            #pragma unroll
            for (int mt = 0; mt < 2; mt++)
                #pragma unroll
                for (int nt = 0; nt < 4; nt++)
                    mma16816(acc[mt][nt], ah[mt], bh[nt >> 1][(nt & 1) * 2], bh[nt >> 1][(nt & 1) * 2 + 1]);
            ldsm4(al[0], aH + ALO + kb);
            ldsm4(al[1], aH + ALO + AMT + kb);
            #pragma unroll
            for (int mt = 0; mt < 2; mt++)
                #pragma unroll
                for (int nt = 0; nt < 4; nt++)
                    mma16816(acc[mt][nt], al[mt], bh[nt >> 1][(nt & 1) * 2], bh[nt >> 1][(nt & 1) * 2 + 1]);
            ldsm4(bl[0], bH + BLO + kb);
            ldsm4(bl[1], bH + BLO + BNT + kb);
            #pragma unroll
            for (int mt = 0; mt < 2; mt++)
                #pragma unroll
                for (int nt = 0; nt < 4; nt++)
                    mma16816(acc[mt][nt], ah[mt], bl[nt >> 1][(nt & 1) * 2], bl[nt >> 1][(nt & 1) * 2 + 1]);
        }
    }

    // ---- epilogue 2 + layer 3 in registers ----
    float part[8];
    #pragma unroll
    for (int i = 0; i < 8; i++) part[i] = 0.f;
    #pragma unroll
    for (int mt = 0; mt < 2; mt++)
        #pragma unroll
        for (int nt = 0; nt < 4; nt++) {
            int r0 = mh * 32 + mt * 16 + g;
            float w2a = sw2[r0], w2b = sw2[r0 + 8];
            float v00 = acc[mt][nt][0] + sb1[r0];     v00 = v00 > 0.f ? v00 : 0.f;
            float v01 = acc[mt][nt][1] + sb1[r0];     v01 = v01 > 0.f ? v01 : 0.f;
            float v10 = acc[mt][nt][2] + sb1[r0 + 8]; v10 = v10 > 0.f ? v10 : 0.f;
            float v11 = acc[mt][nt][3] + sb1[r0 + 8]; v11 = v11 > 0.f ? v11 : 0.f;
            part[nt * 2]     += w2a * v00 + w2b * v10;
            part[nt * 2 + 1] += w2a * v01 + w2b * v11;
        }
    #pragma unroll
    for (int i = 0; i < 8; i++) {
        part[i] += __shfl_xor_sync(0xffffffffu, part[i], 4);
        part[i] += __shfl_xor_sync(0xffffffffu, part[i], 8);
        part[i] += __shfl_xor_sync(0xffffffffu, part[i], 16);
    }
    if (g == 0) {
        #pragma unroll
        for (int nt = 0; nt < 4; nt++) {
            int px0 = ng * 32 + nt * 8 + t * 2;
            sPart[mh * 128 + px0]     = part[nt * 2];
            sPart[mh * 128 + px0 + 1] = part[nt * 2 + 1];
        }
    }
    __syncthreads();

    if (tid < TP) {
        out[(size_t)inst * LL + l0 + tid] = sb2[0] + sPart[tid] + sPart[128 + tid];
    }
}

extern "C" void kernel_launch(void* const* d_in, const int* in_sizes, int n_in,
                              void* d_out, int out_size)
{
    const float* x      = (const float*)d_in[0];
    const float* params = (const float*)d_in[1];
    float* out = (float*)d_out;
    (void)in_sizes; (void)n_in; (void)out_size;

    cudaFuncSetAttribute(condlane_mma_kernel,
                         cudaFuncAttributeMaxDynamicSharedMemorySize, SMEM_TOTAL);

    dim3 gx(LL / TP, 4);
    prep_x_kernel<<<gx, 256>>>(x);
    prep_w_kernel<<<NINST, 256>>>(params);

    dim3 grid(LL / TP, NINST);   // 320 x 32
    condlane_mma_kernel<<<grid, NTHR, SMEM_TOTAL>>>(params, out);
}

// round 15
// speedup vs baseline: 1.8084x; 1.0906x over previous
#include <cuda_runtime.h>
#include <cstdint>

#define CC   64
#define CINN 66
#define LL   40960
#define WW   256
#define TP   128
#define NTHR 256
#define NINST 32
#define NPARAMS 8513

#define OFF_W0 0
#define OFF_W1 4224
#define OFF_W2 8320
#define OFF_B0 8384
#define OFF_B1 8448
#define OFF_B2 8512
#define MASK_BIAS_SHIFT 2.19f

#define KS 72      // word stride per row (288B); swizzled within 8-word groups

// ---- precomputed tf32 operands (device globals; allocation-free) ----
// gX: [img][px][72] tf32 words, k swizzled by (k^px)&7 within 8-groups
__device__ __align__(16) uint32_t gX[4 * LL * KS];
// per instance: W0' (64x72 words, coord cols dropped) | W1 (64x72)
#define WIMG_U32 (2 * 64 * KS)
__device__ __align__(16) uint32_t gWt[NINST * WIMG_U32];

// ---- GEMM smem byte offsets ----
#define W0_O 0          // 18432
#define W1_O 18432      // 18432
#define X_O  36864      // 36864
#define H_O  36864      // H aliases X exactly
#define MISC_O 73728
#define SMEM_TOTAL (MISC_O + 2080)   // 75808 B -> 3 blocks/SM

__device__ __forceinline__ uint32_t f2tf(float v) {
    uint32_t r;
    asm("cvt.rna.tf32.f32 %0, %1;" : "=r"(r) : "f"(v));
    return r;
}
__device__ __forceinline__ uint32_t smem_u32(const void* p) {
    uint32_t a;
    asm("{ .reg .u64 t; cvta.to.shared.u64 t, %1; cvt.u32.u64 %0, t; }" : "=r"(a) : "l"(p));
    return a;
}
__device__ __forceinline__ void cpasync16(uint32_t dst, const void* src) {
    asm volatile("cp.async.cg.shared.global [%0], [%1], 16;" :: "r"(dst), "l"(src) : "memory");
}
__device__ __forceinline__ void mmatf32(float* c, const uint32_t* a, uint32_t b0, uint32_t b1) {
    asm volatile(
        "mma.sync.aligned.m16n8k8.row.col.f32.tf32.tf32.f32 "
        "{%0,%1,%2,%3}, {%4,%5,%6,%7}, {%8,%9}, {%0,%1,%2,%3};"
        : "+f"(c[0]), "+f"(c[1]), "+f"(c[2]), "+f"(c[3])
        : "r"(a[0]), "r"(a[1]), "r"(a[2]), "r"(a[3]), "r"(b0), "r"(b1));
}

// ============ prep kernel 1: X channels -> tf32 swizzled [img][px][72] ============
__global__ __launch_bounds__(256)
void prep_x_kernel(const float* __restrict__ x)
{
    __shared__ __align__(16) float stage[TP * 89];
    const int tile = blockIdx.x;
    const int img  = blockIdx.y;
    const int tid  = threadIdx.x;
    const int l0   = tile * TP;

    const float* xb = x + (size_t)img * CC * LL + l0;
    for (int idx = tid; idx < CC * TP; idx += 256) {
        int ch = idx >> 7, px = idx & 127;
        stage[px * 89 + ch] = xb[(size_t)ch * LL + px];
    }
    __syncthreads();

    for (int idx = tid; idx < TP * KS; idx += 256) {
        int px = idx / KS, k = idx - px * KS;
        float v = (k < CC) ? stage[px * 89 + k] : 0.f;
        int kp = (k & ~7) | ((k ^ px) & 7);      // swizzle within 8-group
        gX[((size_t)img * LL + l0 + px) * KS + kp] = f2tf(v);
    }
}

// ============ prep kernel 2: weights -> tf32 swizzled flat images ============
__global__ __launch_bounds__(256)
void prep_w_kernel(const float* __restrict__ params)
{
    const int inst = blockIdx.x;
    const int tid  = threadIdx.x;
    const float* p = params + (size_t)inst * NPARAMS;
    uint32_t* w = gWt + (size_t)inst * WIMG_U32;

    for (int idx = tid; idx < 64 * KS; idx += 256) {
        int m = idx / KS, k = idx - m * KS;
        int kp = (k & ~7) | ((k ^ m) & 7);
        float v0 = (k < 64) ? p[OFF_W0 + m * CINN + k + 2] : 0.f;   // coord cols dropped
        float v1 = (k < 64) ? p[OFF_W1 + m * 64 + k] : 0.f;
        w[m * KS + kp]            = f2tf(v0);
        w[64 * KS + m * KS + kp]  = f2tf(v1);
    }
}

// ============ main GEMM kernel ============
extern __shared__ __align__(16) char smem[];

__global__ __launch_bounds__(NTHR, 3)
void condlane_mma_kernel(const float* __restrict__ params,
                         float* __restrict__ out)
{
    uint32_t* sw   = (uint32_t*)smem;
    float*    sb0f = (float*)(smem + MISC_O);   // b0 + w0[:,1]*y
    float*    sb1  = sb0f + 64;
    float*    sw2  = sb0f + 128;
    float*    sWx  = sb0f + 192;                // w0[:,0]
    float*    sb2  = sb0f + 256;
    float*    sPart = sb0f + 260;               // [2][128]

    const int bx   = blockIdx.x;
    const int inst = blockIdx.y;
    const int img  = inst >> 3;
    const int tid  = threadIdx.x;
    const int wid  = tid >> 5;
    const int lane = tid & 31;
    const int l0   = bx * TP;
    const uint32_t sb = smem_u32(smem);

    // ---- cp.async copy-in: W (2304 uint4), X (2304 uint4) ----
    {
        const uint4* wsrc = (const uint4*)(gWt + (size_t)inst * WIMG_U32);
        const uint4* xsrc = (const uint4*)(gX + ((size_t)img * LL + l0) * KS);
        for (int i = tid; i < 2304; i += NTHR) {
            cpasync16(sb + i * 16, wsrc + i);
            cpasync16(sb + X_O + i * 16, xsrc + i);
        }
        const float* p = params + (size_t)inst * NPARAMS;
        const float yc = (float)(l0 >> 8);
        if (tid < 64) {
            sb0f[tid] = p[OFF_B0 + tid] + p[OFF_W0 + tid * CINN + 1] * yc;
            sWx[tid]  = p[OFF_W0 + tid * CINN];
            sb1[tid]  = p[OFF_B1 + tid];
            sw2[tid]  = p[OFF_W2 + tid];
        }
        if (tid == 0) sb2[0] = p[OFF_B2] - MASK_BIAS_SHIFT;
        asm volatile("cp.async.commit_group;\ncp.async.wait_group 0;" ::: "memory");
    }
    __syncthreads();

    // ---- warp tiling: 8 warps = (2 m-halves) x (4 px-groups); 32 rows x 32 px ----
    const int mh = wid & 1;
    const int ng = wid >> 1;
    const int g  = lane >> 2;
    const int t  = lane & 3;
    const int swz0 = t ^ g;            // swizzled low-3 k bits for this lane
    const int swz4 = (t + 4) ^ g;

    const float xbase = (float)(l0 & (WW - 1));

    float acc[2][4][4];
    #pragma unroll
    for (int i = 0; i < 2; i++)
        #pragma unroll
        for (int j = 0; j < 4; j++)
            #pragma unroll
            for (int q = 0; q < 4; q++) acc[i][j][q] = 0.f;

    // ======== layer 1: C1 = W0' @ Xc, K=64, single-pass tf32 (8 k8-chunks) ========
    {
        const uint32_t* A = sw + W0_O / 4 + (mh * 32 + g) * KS;
        const uint32_t* B = sw + X_O / 4 + (ng * 32 + g) * KS;
        #pragma unroll
        for (int kc = 0; kc < 8; kc++) {
            int k0 = kc * 8;
            uint32_t a[2][4], b[4][2];
            #pragma unroll
            for (int mt = 0; mt < 2; mt++) {
                const uint32_t* Am = A + mt * 16 * KS + k0;
                a[mt][0] = Am[swz0];
                a[mt][1] = Am[8 * KS + swz0];
                a[mt][2] = Am[swz4];
                a[mt][3] = Am[8 * KS + swz4];
            }
            #pragma unroll
            for (int nt = 0; nt < 4; nt++) {
                const uint32_t* Bn = B + nt * 8 * KS + k0;
                b[nt][0] = Bn[swz0];
                b[nt][1] = Bn[swz4];
            }
            #pragma unroll
            for (int mt = 0; mt < 2; mt++)
                #pragma unroll
                for (int nt = 0; nt < 4; nt++)
                    mmatf32(acc[mt][nt], a[mt], b[nt][0], b[nt][1]);
        }
    }
    __syncthreads();   // all reads of X done before H overwrites it

    // ---- epilogue 1: relu(C1 + b0' + w0x*xcoord) -> H [px][ch] tf32 swizzled ----
    {
        uint32_t* H = sw + H_O / 4;
        #pragma unroll
        for (int mt = 0; mt < 2; mt++)
            #pragma unroll
            for (int nt = 0; nt < 4; nt++) {
                int r0  = mh * 32 + mt * 16 + g;        // r0 & 7 == g
                int rB  = mh * 32 + mt * 16;            // r0 & ~7
                int px0 = ng * 32 + nt * 8 + t * 2;     // px0 & 7 == 2t
                float xc0 = xbase + (float)px0;
                float xc1 = xc0 + 1.f;
                float ba = sb0f[r0],     wa = sWx[r0];
                float bb = sb0f[r0 + 8], wb = sWx[r0 + 8];
                float v00 = acc[mt][nt][0] + ba + wa * xc0; v00 = v00 > 0.f ? v00 : 0.f;
                float v01 = acc[mt][nt][1] + ba + wa * xc1; v01 = v01 > 0.f ? v01 : 0.f;
                float v10 = acc[mt][nt][2] + bb + wb * xc0; v10 = v10 > 0.f ? v10 : 0.f;
                float v11 = acc[mt][nt][3] + bb + wb * xc1; v11 = v11 > 0.f ? v11 : 0.f;
                int s0 = g ^ (2 * t);
                int s1 = g ^ (2 * t + 1);
                H[px0 * KS + rB + s0]            = f2tf(v00);
                H[(px0 + 1) * KS + rB + s1]      = f2tf(v01);
                H[px0 * KS + rB + 8 + s0]        = f2tf(v10);
                H[(px0 + 1) * KS + rB + 8 + s1]  = f2tf(v11);
            }
    }
    __syncthreads();

    // ======== layer 2: C2 = W1 @ H, K=64, single-pass tf32 ========
    #pragma unroll
    for (int i = 0; i < 2; i++)
        #pragma unroll
        for (int j = 0; j < 4; j++)
            #pragma unroll
            for (int q = 0; q < 4; q++) acc[i][j][q] = 0.f;
    {
        const uint32_t* A = sw + W1_O / 4 + (mh * 32 + g) * KS;
        const uint32_t* B = sw + H_O / 4 + (ng * 32 + g) * KS;
        #pragma unroll
        for (int kc = 0; kc < 8; kc++) {
            int k0 = kc * 8;
            uint32_t a[2][4], b[4][2];
            #pragma unroll
            for (int mt = 0; mt < 2; mt++) {
                const uint32_t* Am = A + mt * 16 * KS + k0;
                a[mt][0] = Am[swz0];
                a[mt][1] = Am[8 * KS + swz0];
                a[mt][2] = Am[swz4];
                a[mt][3] = Am[8 * KS + swz4];
            }
            #pragma unroll
            for (int nt = 0; nt < 4; nt++) {
                const uint32_t* Bn = B + nt * 8 * KS + k0;
                b[nt][0] = Bn[swz0];
                b[nt][1] = Bn[swz4];
            }
            #pragma unroll
            for (int mt = 0; mt < 2; mt++)
                #pragma unroll
                for (int nt = 0; nt < 4; nt++)
                    mmatf32(acc[mt][nt], a[mt], b[nt][0], b[nt][1]);
        }
    }

    // ---- epilogue 2 + layer 3 in registers ----
    float part[8];
    #pragma unroll
    for (int i = 0; i < 8; i++) part[i] = 0.f;
    #pragma unroll
    for (int mt = 0; mt < 2; mt++)
        #pragma unroll
        for (int nt = 0; nt < 4; nt++) {
            int r0 = mh * 32 + mt * 16 + g;
            float w2a = sw2[r0], w2b = sw2[r0 + 8];
            float v00 = acc[mt][nt][0] + sb1[r0];     v00 = v00 > 0.f ? v00 : 0.f;
            float v01 = acc[mt][nt][1] + sb1[r0];     v01 = v01 > 0.f ? v01 : 0.f;
            float v10 = acc[mt][nt][2] + sb1[r0 + 8]; v10 = v10 > 0.f ? v10 : 0.f;
            float v11 = acc[mt][nt][3] + sb1[r0 + 8]; v11 = v11 > 0.f ? v11 : 0.f;
            part[nt * 2]     += w2a * v00 + w2b * v10;
            part[nt * 2 + 1] += w2a * v01 + w2b * v11;
        }
    #pragma unroll
    for (int i = 0; i < 8; i++) {
        part[i] += __shfl_xor_sync(0xffffffffu, part[i], 4);
        part[i] += __shfl_xor_sync(0xffffffffu, part[i], 8);
        part[i] += __shfl_xor_sync(0xffffffffu, part[i], 16);
    }
    if (g == 0) {
        #pragma unroll
        for (int nt = 0; nt < 4; nt++) {
            int px0 = ng * 32 + nt * 8 + t * 2;
            sPart[mh * 128 + px0]     = part[nt * 2];
            sPart[mh * 128 + px0 + 1] = part[nt * 2 + 1];
        }
    }
    __syncthreads();

    if (tid < TP) {
        out[(size_t)inst * LL + l0 + tid] = sb2[0] + sPart[tid] + sPart[128 + tid];
    }
}

extern "C" void kernel_launch(void* const* d_in, const int* in_sizes, int n_in,
                              void* d_out, int out_size)
{
    const float* x      = (const float*)d_in[0];
    const float* params = (const float*)d_in[1];
    float* out = (float*)d_out;
    (void)in_sizes; (void)n_in; (void)out_size;

    cudaFuncSetAttribute(condlane_mma_kernel,
                         cudaFuncAttributeMaxDynamicSharedMemorySize, SMEM_TOTAL);

    dim3 gx(LL / TP, 4);
    prep_x_kernel<<<gx, 256>>>(x);
    prep_w_kernel<<<NINST, 256>>>(params);

    dim3 grid(LL / TP, NINST);   // 320 x 32
    condlane_mma_kernel<<<grid, NTHR, SMEM_TOTAL>>>(params, out);
}